// round 8
// baseline (speedup 1.0000x reference)
#include <cuda_runtime.h>
#include <math.h>

#define BATCH 16
#define HH 512
#define WW 512
#define WIN 15
#define RAD 7
#define OTC 112                 // output cols per tile (4 static strips of 28)
#define OTR 64                  // output rows per tile
#define GRX 5                   // tiles 0..3 full (112), tile 4 = 64 cols
#define GRY 8
#define NT 256
#define NBLOCKS (GRX * GRY * BATCH)   // 640
#define VP 129                  // smem pitch in float2
#define GROWS 47                // 1 zero row + 46 prefix rows per group

#define SMEM_BYTES (2 * GROWS * VP * 8)   // 97,008 bytes

__device__ double g_part[NBLOCKS][8];
__device__ unsigned int g_count = 0;

extern __shared__ float2 smem2[];

__global__ void __launch_bounds__(NT, 2)
ncc_main(const float* __restrict__ I, const float* __restrict__ J,
         float* __restrict__ out) {
    float2* vS = smem2;   // [2 groups][47 rows][<=128 cols], pitch 129 float2

    const int tid = threadIdx.x;
    const int bx = blockIdx.x, by = blockIdx.y, bz = blockIdx.z;
    const float* __restrict__ Ib = I + (size_t)bz * HH * WW;
    const float* __restrict__ Jb = J + (size_t)bz * HH * WW;

    // ========== Phase A: vertical RUNNING PREFIX per column ==================
    // 2 groups x 128 columns; group g streams rows [g*32-7, g*32+38] of the
    // tile and stores prefix-after-each-row. No ring, no reload: each load's
    // only consumer is one FADD into the prefix -> ptxas can batch loads deep.
    const int tx      = tid & 127;
    const int g       = tid >> 7;
    const int rowbase = by * OTR + g * 32 - RAD;
    const int gx      = bx * OTC - RAD + tx;
    const bool colok  = (gx >= 0) && (gx < WW);
    const bool ownx   = colok && (tx >= RAD) && (tx < RAD + OTC);
    const float wx = ownx ? (float)(min(gx + RAD, WW - 1) - max(gx - RAD, 0) + 1) : 0.f;

    float PI = 0.f, PJ = 0.f;
    float pII = 0.f, pJJ = 0.f, pIJ = 0.f;
    const int sbase = g * GROWS;

    vS[sbase * VP + tx] = make_float2(0.f, 0.f);     // P[-1] = 0
    #pragma unroll
    for (int r = 0; r < 46; r++) {
        const int gy = rowbase + r;
        float vi = 0.f, vj = 0.f;
        if (colok && gy >= 0 && gy < HH) {
            const int gi = gy * WW + gx;
            vi = __ldg(Ib + gi);
            vj = __ldg(Jb + gi);
        }
        PI += vi; PJ += vj;
        if (r >= RAD && r < RAD + 32 && ownx) {       // owned input pixel
            const float wy = (float)(min(gy + RAD, HH - 1) - max(gy - RAD, 0) + 1);
            const float w = wy * wx;
            pII += w * vi * vi;
            pJJ += w * vj * vj;
            pIJ += w * vi * vj;
        }
        vS[(sbase + 1 + r) * VP + tx] = make_float2(PI, PJ);
    }
    __syncthreads();

    // ========== Phase B: vertical window = prefix diff; horizontal slide =====
    // row = tid>>2 (0..63): gq = row>>5, k = row&31; q = tid&3 -> 28-col strip.
    const int row = tid >> 2;
    const int gq  = row >> 5;
    const int k   = row & 31;
    const int q   = tid & 3;
    const int oc0 = q * 28;
    const float2* lo = vS + (gq * GROWS + k) * VP;        // P[k-1]
    const float2* hi = vS + (gq * GROWS + k + WIN) * VP;  // P[k+14]

    float sII = 0.f, sJJ = 0.f, sIJ = 0.f;
    if (bx < GRX - 1) {
        float2 bring[WIN];
        float aSI = 0.f, aSJ = 0.f;
        #pragma unroll
        for (int kk = 0; kk < WIN; kk++) {
            float2 h = hi[oc0 + kk], l = lo[oc0 + kk];
            float2 v = make_float2(h.x - l.x, h.y - l.y);
            bring[kk] = v;
            aSI += v.x; aSJ += v.y;
        }
        #pragma unroll
        for (int i = 0; i < 28; i++) {
            sII += aSI * aSI;
            sJJ += aSJ * aSJ;
            sIJ += aSI * aSJ;
            if (i < 27) {
                float2 h = hi[oc0 + i + WIN], l = lo[oc0 + i + WIN];
                float2 vn = make_float2(h.x - l.x, h.y - l.y);
                float2 vo = bring[i % WIN];
                aSI += vn.x - vo.x;
                aSJ += vn.y - vo.y;
                bring[i % WIN] = vn;
            }
        }
    } else {
        const int ncols = WW - (GRX - 1) * OTC;   // 64
        float2 bring[WIN];
        float aSI = 0.f, aSJ = 0.f;
        #pragma unroll
        for (int kk = 0; kk < WIN; kk++) {
            float2 h = hi[oc0 + kk], l = lo[oc0 + kk];
            float2 v = make_float2(h.x - l.x, h.y - l.y);
            bring[kk] = v;
            aSI += v.x; aSJ += v.y;
        }
        #pragma unroll
        for (int i = 0; i < 28; i++) {
            const int oc = oc0 + i;
            if (oc < ncols) {
                sII += aSI * aSI;
                sJJ += aSJ * aSJ;
                sIJ += aSI * aSJ;
            }
            if (i < 27 && oc < ncols - 1) {
                float2 h = hi[oc + WIN], l = lo[oc + WIN];
                float2 vn = make_float2(h.x - l.x, h.y - l.y);
                float2 vo = bring[i % WIN];
                aSI += vn.x - vo.x;
                aSJ += vn.y - vo.y;
                bring[i % WIN] = vn;
            }
        }
    }

    // ===================== Per-CTA reduction (double) ========================
    double a0 = (double)pII, a1 = (double)pJJ, a2 = (double)pIJ;
    double a3 = (double)sII, a4 = (double)sJJ, a5 = (double)sIJ;
    #pragma unroll
    for (int off = 16; off > 0; off >>= 1) {
        a0 += __shfl_xor_sync(0xFFFFFFFFu, a0, off);
        a1 += __shfl_xor_sync(0xFFFFFFFFu, a1, off);
        a2 += __shfl_xor_sync(0xFFFFFFFFu, a2, off);
        a3 += __shfl_xor_sync(0xFFFFFFFFu, a3, off);
        a4 += __shfl_xor_sync(0xFFFFFFFFu, a4, off);
        a5 += __shfl_xor_sync(0xFFFFFFFFu, a5, off);
    }
    __syncthreads();                       // all phase-B smem reads done
    double* red = (double*)smem2;          // 8 warps x 6 doubles
    const int lane = tid & 31;
    const int warp = tid >> 5;
    if (lane == 0) {
        red[warp * 6 + 0] = a0; red[warp * 6 + 1] = a1; red[warp * 6 + 2] = a2;
        red[warp * 6 + 3] = a3; red[warp * 6 + 4] = a4; red[warp * 6 + 5] = a5;
    }
    __syncthreads();

    const int bid = bx + GRX * (by + GRY * bz);
    __shared__ int s_last;
    if (tid == 0) {
        double t0 = 0, t1 = 0, t2 = 0, t3 = 0, t4 = 0, t5 = 0;
        #pragma unroll
        for (int w = 0; w < NT / 32; w++) {
            t0 += red[w * 6 + 0]; t1 += red[w * 6 + 1]; t2 += red[w * 6 + 2];
            t3 += red[w * 6 + 3]; t4 += red[w * 6 + 4]; t5 += red[w * 6 + 5];
        }
        g_part[bid][0] = t0; g_part[bid][1] = t1; g_part[bid][2] = t2;
        g_part[bid][3] = t3; g_part[bid][4] = t4; g_part[bid][5] = t5;
        __threadfence();
        unsigned int prev = atomicAdd(&g_count, 1u);
        s_last = (prev == NBLOCKS - 1);
    }
    __syncthreads();

    // ================= Last CTA: global reduce + finalize ====================
    if (s_last) {
        double c0 = 0, c1 = 0, c2 = 0, c3 = 0, c4 = 0, c5 = 0;
        for (int c = tid; c < NBLOCKS; c += NT) {
            c0 += g_part[c][0]; c1 += g_part[c][1]; c2 += g_part[c][2];
            c3 += g_part[c][3]; c4 += g_part[c][4]; c5 += g_part[c][5];
        }
        #pragma unroll
        for (int off = 16; off > 0; off >>= 1) {
            c0 += __shfl_xor_sync(0xFFFFFFFFu, c0, off);
            c1 += __shfl_xor_sync(0xFFFFFFFFu, c1, off);
            c2 += __shfl_xor_sync(0xFFFFFFFFu, c2, off);
            c3 += __shfl_xor_sync(0xFFFFFFFFu, c3, off);
            c4 += __shfl_xor_sync(0xFFFFFFFFu, c4, off);
            c5 += __shfl_xor_sync(0xFFFFFFFFu, c5, off);
        }
        __syncthreads();
        if (lane == 0) {
            red[warp * 6 + 0] = c0; red[warp * 6 + 1] = c1; red[warp * 6 + 2] = c2;
            red[warp * 6 + 3] = c3; red[warp * 6 + 4] = c4; red[warp * 6 + 5] = c5;
        }
        __syncthreads();
        if (tid == 0) {
            double t0 = 0, t1 = 0, t2 = 0, t3 = 0, t4 = 0, t5 = 0;
            #pragma unroll
            for (int w = 0; w < NT / 32; w++) {
                t0 += red[w * 6 + 0]; t1 += red[w * 6 + 1]; t2 += red[w * 6 + 2];
                t3 += red[w * 6 + 3]; t4 += red[w * 6 + 4]; t5 += red[w * 6 + 5];
            }
            const double inv = 1.0 / 225.0;
            double cross = t2 - t5 * inv;
            double iv    = t0 - t3 * inv;
            double jv    = t1 - t4 * inv;
            out[0] = (float)(-(cross / sqrt(iv * jv)));
            g_count = 0;    // reset for next graph replay
        }
    }
}

extern "C" void kernel_launch(void* const* d_in, const int* in_sizes, int n_in,
                              void* d_out, int out_size) {
    const float* I = (const float*)d_in[0];
    const float* J = (const float*)d_in[1];
    float* out = (float*)d_out;

    cudaFuncSetAttribute(ncc_main,
                         cudaFuncAttributeMaxDynamicSharedMemorySize, SMEM_BYTES);
    dim3 grid(GRX, GRY, BATCH);   // (5, 8, 16) = 640 CTAs
    ncc_main<<<grid, NT, SMEM_BYTES>>>(I, J, out);
}